// round 1
// baseline (speedup 1.0000x reference)
#include <cuda_runtime.h>
#include <cuda_bf16.h>
#include <cstddef>

#define NSAMP 16384
#define HID   512
#define DIN   128
#define EOBS  4096
#define KOBS  40
#define DTF   0.05f

// ---------------- device scratch (no allocs allowed) ----------------
__device__ float g_h [NSAMP * HID];   // hidden state, 32 MB
__device__ float g_t [NSAMP * HID];   // tanh intermediate, 32 MB
__device__ float g_p1[EOBS  * HID];   // relu intermediate, 8 MB
__device__ float g_hn[EOBS  * HID];   // rnn-cell output before scatter, 8 MB
__device__ double g_loss;
__device__ double g_totm;

// ---------------- modes ----------------
#define MODE_TANH    0   // C = tanh(acc + bias)                    (euler gemm1)
#define MODE_EULER   1   // C = C + DT*(acc + bias)                 (euler gemm2)
#define MODE_RELU_G  2   // gather A; C = relu(acc + bias)          (p_model L1)
#define MODE_STORE   3   // C = acc                                  (rnn X @ W_ih^T)
#define MODE_TANH2_G 4   // gather A; C = tanh(acc + C + b1 + b2)   (rnn cell)
#define MODE_LOSS    5   // p = acc+bias; reduce |X-p|*M and M       (p_model L2 + loss)

__host__ __device__ constexpr bool mode_gathers(int m) { return m == MODE_RELU_G || m == MODE_TANH2_G; }

// ---------------- tiled SGEMM: C[M,NOUT] = epilogue(A[M,K] @ W[NOUT,K]^T) ----------------
// BM=BN=128, BK=8, 256 threads, 8x8 microtile (split 4+4 in each dim).
#define BM 128
#define BN 128
#define BK 8

template<int MODE, int KDIM, int NOUT>
__global__ __launch_bounds__(256, 2)
void gemm_kernel(const float* __restrict__ A,
                 const float* __restrict__ W,
                 const float* __restrict__ bias,
                 const float* __restrict__ bias2,
                 float* __restrict__ C,
                 const int* __restrict__ gidx,
                 const float* __restrict__ Xo,
                 const float* __restrict__ Mo)
{
    __shared__ float As[BK][BM];
    __shared__ float Ws[BK][BN];
    __shared__ int   sIdx[BM];
    __shared__ float redL[256];
    __shared__ float redM[256];

    const int tid = threadIdx.x;
    const int tx  = tid & 15;      // 0..15
    const int ty  = tid >> 4;      // 0..15
    const int rowbase = blockIdx.y * BM;
    const int colbase = blockIdx.x * BN;

    if (mode_gathers(MODE)) {
        if (tid < BM) sIdx[tid] = gidx[rowbase + tid];
        __syncthreads();
    }

    // global load assignment: each thread loads one float4 of A and one of W per k-tile
    const int aRow = tid >> 1;          // 0..127
    const int aK   = (tid & 1) * 4;     // 0 or 4

    const float* Aptr;
    if (mode_gathers(MODE)) Aptr = A + (size_t)sIdx[aRow] * KDIM + aK;
    else                    Aptr = A + (size_t)(rowbase + aRow) * KDIM + aK;
    const float* Wptr = W + (size_t)(colbase + aRow) * KDIM + aK;

    float acc[8][8];
#pragma unroll
    for (int i = 0; i < 8; i++)
#pragma unroll
        for (int j = 0; j < 8; j++) acc[i][j] = 0.f;

    float4 av = *(const float4*)(Aptr);
    float4 wv = *(const float4*)(Wptr);

#pragma unroll 1
    for (int k0 = 0; k0 < KDIM; k0 += BK) {
        __syncthreads();
        As[aK + 0][aRow] = av.x; As[aK + 1][aRow] = av.y;
        As[aK + 2][aRow] = av.z; As[aK + 3][aRow] = av.w;
        Ws[aK + 0][aRow] = wv.x; Ws[aK + 1][aRow] = wv.y;
        Ws[aK + 2][aRow] = wv.z; Ws[aK + 3][aRow] = wv.w;
        __syncthreads();
        if (k0 + BK < KDIM) {
            av = *(const float4*)(Aptr + k0 + BK);
            wv = *(const float4*)(Wptr + k0 + BK);
        }
#pragma unroll
        for (int k = 0; k < BK; k++) {
            float ra[8], rw[8];
            *(float4*)(ra)     = *(const float4*)&As[k][ty * 4];
            *(float4*)(ra + 4) = *(const float4*)&As[k][64 + ty * 4];
            *(float4*)(rw)     = *(const float4*)&Ws[k][tx * 4];
            *(float4*)(rw + 4) = *(const float4*)&Ws[k][64 + tx * 4];
#pragma unroll
            for (int i = 0; i < 8; i++)
#pragma unroll
                for (int j = 0; j < 8; j++)
                    acc[i][j] += ra[i] * rw[j];
        }
    }

    // ---------------- epilogue ----------------
    float lsum = 0.f, msum = 0.f;

#pragma unroll
    for (int rh = 0; rh < 2; rh++) {
#pragma unroll
        for (int ri = 0; ri < 4; ri++) {
            const int ar   = rh * 4 + ri;
            const int grow = rowbase + rh * 64 + ty * 4 + ri;
#pragma unroll
            for (int ch = 0; ch < 2; ch++) {
                const int gcol = colbase + ch * 64 + tx * 4;
                if constexpr (MODE == MODE_LOSS) {
#pragma unroll
                    for (int cj = 0; cj < 4; cj++) {
                        float p = acc[ar][ch * 4 + cj] + bias[gcol + cj];
                        float x = Xo[(size_t)grow * NOUT + gcol + cj];
                        float m = Mo[(size_t)grow * NOUT + gcol + cj];
                        lsum += fabsf(x - p) * m;
                        msum += m;
                    }
                } else {
                    float4 out;
                    float* po = &out.x;
                    if constexpr (MODE == MODE_TANH) {
#pragma unroll
                        for (int cj = 0; cj < 4; cj++)
                            po[cj] = tanhf(acc[ar][ch * 4 + cj] + bias[gcol + cj]);
                    } else if constexpr (MODE == MODE_EULER) {
                        float4 cold = *(const float4*)&C[(size_t)grow * NOUT + gcol];
                        const float* pc = &cold.x;
#pragma unroll
                        for (int cj = 0; cj < 4; cj++)
                            po[cj] = pc[cj] + DTF * (acc[ar][ch * 4 + cj] + bias[gcol + cj]);
                    } else if constexpr (MODE == MODE_RELU_G) {
#pragma unroll
                        for (int cj = 0; cj < 4; cj++) {
                            float v = acc[ar][ch * 4 + cj] + bias[gcol + cj];
                            po[cj] = v > 0.f ? v : 0.f;
                        }
                    } else if constexpr (MODE == MODE_STORE) {
#pragma unroll
                        for (int cj = 0; cj < 4; cj++)
                            po[cj] = acc[ar][ch * 4 + cj];
                    } else { // MODE_TANH2_G
                        float4 cold = *(const float4*)&C[(size_t)grow * NOUT + gcol];
                        const float* pc = &cold.x;
#pragma unroll
                        for (int cj = 0; cj < 4; cj++)
                            po[cj] = tanhf(acc[ar][ch * 4 + cj] + pc[cj]
                                           + bias[gcol + cj] + bias2[gcol + cj]);
                    }
                    *(float4*)&C[(size_t)grow * NOUT + gcol] = out;
                }
            }
        }
    }

    if constexpr (MODE == MODE_LOSS) {
        redL[tid] = lsum;
        redM[tid] = msum;
        __syncthreads();
#pragma unroll
        for (int s = 128; s > 0; s >>= 1) {
            if (tid < s) { redL[tid] += redL[tid + s]; redM[tid] += redM[tid + s]; }
            __syncthreads();
        }
        if (tid == 0) {
            atomicAdd(&g_loss, (double)redL[0]);
            atomicAdd(&g_totm, (double)redM[0]);
        }
    }
}

// ---------------- small kernels ----------------
__global__ void init_kernel(float* __restrict__ h)
{
    size_t i = (size_t)blockIdx.x * blockDim.x + threadIdx.x;
    ((float4*)h)[i] = make_float4(0.f, 0.f, 0.f, 0.f);
    if (i == 0) { g_loss = 0.0; g_totm = 0.0; }
}

__global__ void scatter_kernel(const int* __restrict__ idx,
                               const float* __restrict__ src,
                               float* __restrict__ dst)
{
    int r = blockIdx.x;          // 0..EOBS-1
    int c = threadIdx.x;         // 0..127 (float4 units over HID=512)
    float4 v = ((const float4*)(src + (size_t)r * HID))[c];
    ((float4*)(dst + (size_t)idx[r] * HID))[c] = v;
}

__global__ void final_kernel(float* __restrict__ out)
{
    out[0] = (float)g_loss;
    out[1] = (float)(g_loss / g_totm);
}

// ---------------- launch ----------------
extern "C" void kernel_launch(void* const* d_in, const int* in_sizes, int n_in,
                              void* d_out, int out_size)
{
    const float* X    = (const float*)d_in[0];
    const float* Mm   = (const float*)d_in[1];
    const int*   bidx = (const int*)  d_in[2];
    const float* W_ih = (const float*)d_in[3];
    const float* b_ih = (const float*)d_in[4];
    const float* W_hh = (const float*)d_in[5];
    const float* b_hh = (const float*)d_in[6];
    const float* Wo1  = (const float*)d_in[7];
    const float* bo1  = (const float*)d_in[8];
    const float* Wo2  = (const float*)d_in[9];
    const float* bo2  = (const float*)d_in[10];
    const float* Wp1  = (const float*)d_in[11];
    const float* bp1  = (const float*)d_in[12];
    const float* Wp2  = (const float*)d_in[13];
    const float* bp2  = (const float*)d_in[14];

    float *h, *t, *p1, *hn;
    cudaGetSymbolAddress((void**)&h,  g_h);
    cudaGetSymbolAddress((void**)&t,  g_t);
    cudaGetSymbolAddress((void**)&p1, g_p1);
    cudaGetSymbolAddress((void**)&hn, g_hn);

    // zero hidden state + accumulators (runs on every graph replay)
    init_kernel<<<(NSAMP * HID / 4) / 256, 256>>>(h);

    const dim3 gEuler(HID / BN, NSAMP / BM);  // (4, 128)
    const dim3 gObs  (HID / BN, EOBS  / BM);  // (4, 32)
    const dim3 gLoss (DIN / BN, EOBS  / BM);  // (1, 32)

    for (int s = 0; s < KOBS; s++) {
        const float* Xs = X  + (size_t)s * EOBS * DIN;
        const float* Ms = Mm + (size_t)s * EOBS * DIN;
        const int*   is = bidx + (size_t)s * EOBS;

        // 2 Euler steps on all N samples
        for (int e = 0; e < 2; e++) {
            gemm_kernel<MODE_TANH,  HID, HID><<<gEuler, 256>>>(h, Wo1, bo1, nullptr, t, nullptr, nullptr, nullptr);
            gemm_kernel<MODE_EULER, HID, HID><<<gEuler, 256>>>(t, Wo2, bo2, nullptr, h, nullptr, nullptr, nullptr);
        }
        // p_model layer 1 (gather h[idx]) -> relu
        gemm_kernel<MODE_RELU_G, HID, HID><<<gObs, 256>>>(h, Wp1, bp1, nullptr, p1, is, nullptr, nullptr);
        // p_model layer 2 fused with MAE loss + mask-sum reduction
        gemm_kernel<MODE_LOSS, HID, DIN><<<gLoss, 256>>>(p1, Wp2, bp2, nullptr, nullptr, nullptr, Xs, Ms);
        // RNN cell: hn = X @ W_ih^T ; hn = tanh(hn + h[idx] @ W_hh^T + b_ih + b_hh)
        gemm_kernel<MODE_STORE,   DIN, HID><<<gObs, 256>>>(Xs, W_ih, nullptr, nullptr, hn, nullptr, nullptr, nullptr);
        gemm_kernel<MODE_TANH2_G, HID, HID><<<gObs, 256>>>(h, W_hh, b_ih, b_hh, hn, is, nullptr, nullptr);
        // scatter updated rows back into h
        scatter_kernel<<<EOBS, 128>>>(is, hn, h);
    }
    // NOTE: the 10 prop_to_end Euler steps are provably output-invariant -> skipped.

    final_kernel<<<1, 1>>>((float*)d_out);
}

// round 3
// speedup vs baseline: 2.2015x; 2.2015x over previous
#include <cuda_runtime.h>
#include <cuda_bf16.h>
#include <cstdint>
#include <cstddef>

#define NSAMP 16384
#define HID   512
#define DIN   128
#define EOBS  4096
#define KOBS  40
#define DTF   0.05f

#define MODE_TANH    0
#define MODE_EULER   1
#define MODE_RELU_G  2
#define MODE_STORE   3
#define MODE_TANH2_G 4
#define MODE_LOSS    5

// ------------------------------------------------------------------
// Device scratch (no allocations allowed)
// ------------------------------------------------------------------
__device__ float         g_h   [(size_t)NSAMP*HID];
__device__ __nv_bfloat16 g_h_hi[(size_t)NSAMP*HID];
__device__ __nv_bfloat16 g_h_lo[(size_t)NSAMP*HID];
__device__ __nv_bfloat16 g_t_hi[(size_t)NSAMP*HID];
__device__ __nv_bfloat16 g_t_lo[(size_t)NSAMP*HID];
__device__ __nv_bfloat16 g_p1_hi[(size_t)EOBS*HID];
__device__ __nv_bfloat16 g_p1_lo[(size_t)EOBS*HID];
__device__ float         g_hn   [(size_t)EOBS*HID];
__device__ __nv_bfloat16 g_hn_hi[(size_t)EOBS*HID];
__device__ __nv_bfloat16 g_hn_lo[(size_t)EOBS*HID];
__device__ __nv_bfloat16 g_X_hi[(size_t)KOBS*EOBS*DIN];
__device__ __nv_bfloat16 g_X_lo[(size_t)KOBS*EOBS*DIN];

__device__ __nv_bfloat16 g_Wih_hi[HID*DIN],  g_Wih_lo[HID*DIN];
__device__ __nv_bfloat16 g_Whh_hi[HID*HID],  g_Whh_lo[HID*HID];
__device__ __nv_bfloat16 g_Wo1_hi[HID*HID],  g_Wo1_lo[HID*HID];
__device__ __nv_bfloat16 g_Wo2_hi[HID*HID],  g_Wo2_lo[HID*HID];
__device__ __nv_bfloat16 g_Wp1_hi[HID*HID],  g_Wp1_lo[HID*HID];
__device__ __nv_bfloat16 g_Wp2_hi[DIN*HID],  g_Wp2_lo[DIN*HID];

__device__ double g_loss;
__device__ double g_totm;

// ------------------------------------------------------------------
// PTX helpers (all portable: sm_80+ features only)
// ------------------------------------------------------------------
__device__ __forceinline__ uint32_t smem_u32(const void* p) {
    uint32_t a;
    asm("{ .reg .u64 t; cvta.to.shared.u64 t, %1; cvt.u32.u64 %0, t; }" : "=r"(a) : "l"(p));
    return a;
}
__device__ __forceinline__ void cp16(uint32_t dst, const void* src) {
    asm volatile("cp.async.cg.shared.global [%0], [%1], 16;" :: "r"(dst), "l"(src) : "memory");
}
__device__ __forceinline__ void cp_commit() {
    asm volatile("cp.async.commit_group;" ::: "memory");
}
template<int N>
__device__ __forceinline__ void cp_wait() {
    asm volatile("cp.async.wait_group %0;" :: "n"(N) : "memory");
}
__device__ __forceinline__ void ldm4(uint32_t* r, uint32_t addr) {
    asm volatile("ldmatrix.sync.aligned.m8n8.x4.shared.b16 {%0,%1,%2,%3}, [%4];"
                 : "=r"(r[0]), "=r"(r[1]), "=r"(r[2]), "=r"(r[3]) : "r"(addr));
}
__device__ __forceinline__ void mma16816(float* d, const uint32_t* a, const uint32_t* b) {
    asm volatile(
        "mma.sync.aligned.m16n8k16.row.col.f32.bf16.bf16.f32 "
        "{%0,%1,%2,%3}, {%4,%5,%6,%7}, {%8,%9}, {%0,%1,%2,%3};"
        : "+f"(d[0]), "+f"(d[1]), "+f"(d[2]), "+f"(d[3])
        : "r"(a[0]), "r"(a[1]), "r"(a[2]), "r"(a[3]), "r"(b[0]), "r"(b[1]));
}

// SMEM plan: [align pad ≤1024][2 stages × 4 mats × 16KB][ctrl 1KB]
#define TILE_BYTES   16384
#define STAGE_BYTES  65536
#define SMEM_DYN     (2*STAGE_BYTES + 1024 + 1024)

// ------------------------------------------------------------------
// Tensor-core GEMM (mma.sync): C[M,NOUT] = epi(A[M,KDIM] @ W[NOUT,KDIM]^T)
// A,W as bf16 hi/lo splits; product = Ah*Bh + Ah*Bl + Al*Bh (fp32 accum).
// CTA tile 128x128, 8 warps (4 row x 2 col), warp tile 32x64.
// ------------------------------------------------------------------
template<int MODE, int KDIM, int NOUT>
__global__ __launch_bounds__(256, 1)
void mma_gemm(const __nv_bfloat16* __restrict__ Ah, const __nv_bfloat16* __restrict__ Al,
              const __nv_bfloat16* __restrict__ Bh, const __nv_bfloat16* __restrict__ Bl,
              const float* __restrict__ bias, const float* __restrict__ bias2,
              const float* __restrict__ Cin,  float* __restrict__ Cout,
              __nv_bfloat16* __restrict__ Ohi, __nv_bfloat16* __restrict__ Olo,
              const int* __restrict__ gidx,
              const float* __restrict__ Xo, const float* __restrict__ Mo)
{
    constexpr int  NC     = KDIM / 64;
    constexpr bool GATHER = (MODE == MODE_RELU_G || MODE == MODE_TANH2_G);

    extern __shared__ char smraw[];
    const uint32_t sbase = smem_u32(smraw);
    const uint32_t tbase = (sbase + 1023u) & ~1023u;
    char* ctrlp = smraw + (tbase - sbase) + 2 * STAGE_BYTES;
    int*   sIdx = (int*)ctrlp;            // 128 ints
    float* redL = (float*)(ctrlp + 512);  // 8 floats
    float* redM = (float*)(ctrlp + 544);  // 8 floats

    const int tid = threadIdx.x, wid = tid >> 5, lid = tid & 31;
    const int rowbase = blockIdx.y * 128;
    const int colbase = blockIdx.x * 128;
    const int wr = wid & 3, wc = wid >> 2;

    if (GATHER) {
        if (tid < 128) sIdx[tid] = gidx[rowbase + tid];
        __syncthreads();
    }

    // ---- async chunk loader: 4 mats × 128 rows × 128B, SW128-swizzled ----
    auto load_chunk = [&](int kc, int stage) {
        const uint32_t sb = tbase + (uint32_t)stage * STAGE_BYTES;
#pragma unroll
        for (int u = 0; u < 16; u++) {
            const int mat = u >> 2;                  // 0:Ah 1:Al 2:Bh 3:Bl
            const int rem = (u & 3) * 256 + tid;
            const int row = rem >> 3;
            const int un  = rem & 7;
            const __nv_bfloat16* src;
            if (mat < 2) {
                int rg = GATHER ? sIdx[row] : (rowbase + row);
                src = (mat == 0 ? Ah : Al) + (size_t)rg * KDIM + kc * 64 + un * 8;
            } else {
                int rg = colbase + row;
                src = (mat == 2 ? Bh : Bl) + (size_t)rg * KDIM + kc * 64 + un * 8;
            }
            uint32_t off = (uint32_t)(row * 128 + un * 16);
            off ^= (off >> 3) & 0x70;
            cp16(sb + (uint32_t)mat * TILE_BYTES + off, src);
        }
    };

    float acc[2][8][4];
#pragma unroll
    for (int i = 0; i < 2; i++)
#pragma unroll
        for (int j = 0; j < 8; j++)
#pragma unroll
            for (int q = 0; q < 4; q++) acc[i][j][q] = 0.f;

    // ---- compute one 64-wide K chunk from a stage ----
    auto compute = [&](int stage) {
        const uint32_t sb = tbase + (uint32_t)stage * STAGE_BYTES;
#pragma unroll
        for (int k16 = 0; k16 < 4; k16++) {
            uint32_t ah[2][4], al[2][4];
#pragma unroll
            for (int mi = 0; mi < 2; mi++) {
                uint32_t off = (uint32_t)((wr * 32 + mi * 16 + (lid & 15)) * 128
                                          + k16 * 32 + (lid >> 4) * 16);
                off ^= (off >> 3) & 0x70;
                ldm4(ah[mi], sb + off);
                ldm4(al[mi], sb + TILE_BYTES + off);
            }
            uint32_t bh[4][4], bl[4][4];
#pragma unroll
            for (int nb = 0; nb < 4; nb++) {
                uint32_t off = (uint32_t)((wc * 64 + nb * 16 + (lid & 7) + ((lid >> 4) & 1) * 8) * 128
                                          + k16 * 32 + ((lid >> 3) & 1) * 16);
                off ^= (off >> 3) & 0x70;
                ldm4(bh[nb], sb + 2 * TILE_BYTES + off);
                ldm4(bl[nb], sb + 3 * TILE_BYTES + off);
            }
#pragma unroll
            for (int mi = 0; mi < 2; mi++)
#pragma unroll
                for (int na = 0; na < 8; na++) {
                    const uint32_t* Bh2 = &bh[na >> 1][(na & 1) * 2];
                    const uint32_t* Bl2 = &bl[na >> 1][(na & 1) * 2];
                    mma16816(acc[mi][na], ah[mi], Bh2);
                    mma16816(acc[mi][na], ah[mi], Bl2);
                    mma16816(acc[mi][na], al[mi], Bh2);
                }
        }
    };

    // ---- pipelined mainloop ----
    load_chunk(0, 0); cp_commit();
#pragma unroll 1
    for (int c = 0; c < NC; c++) {
        if (c + 1 < NC) { load_chunk(c + 1, (c + 1) & 1); cp_commit(); cp_wait<1>(); }
        else            { cp_wait<0>(); }
        __syncthreads();
        compute(c & 1);
        __syncthreads();
    }

    // ---- epilogue from register accumulators ----
    float lsum = 0.f, msum = 0.f;
#pragma unroll
    for (int mi = 0; mi < 2; mi++) {
#pragma unroll
        for (int hh = 0; hh < 2; hh++) {
            const int row = rowbase + wr * 32 + mi * 16 + (lid >> 2) + hh * 8;
#pragma unroll
            for (int na = 0; na < 8; na++) {
                const int c = colbase + wc * 64 + na * 8 + (lid & 3) * 2;
                float v0 = acc[mi][na][hh * 2 + 0];
                float v1 = acc[mi][na][hh * 2 + 1];
                if constexpr (MODE == MODE_LOSS) {
                    float2 bb = *(const float2*)(bias + c);
                    float2 xx = *(const float2*)(Xo + (size_t)row * NOUT + c);
                    float2 mm = *(const float2*)(Mo + (size_t)row * NOUT + c);
                    lsum += fabsf(xx.x - (v0 + bb.x)) * mm.x + fabsf(xx.y - (v1 + bb.y)) * mm.y;
                    msum += mm.x + mm.y;
                } else {
                    if constexpr (MODE == MODE_TANH) {
                        float2 bb = *(const float2*)(bias + c);
                        v0 = tanhf(v0 + bb.x); v1 = tanhf(v1 + bb.y);
                    } else if constexpr (MODE == MODE_EULER) {
                        float2 bb = *(const float2*)(bias + c);
                        float2 hh2 = *(const float2*)(Cin + (size_t)row * NOUT + c);
                        v0 = hh2.x + DTF * (v0 + bb.x); v1 = hh2.y + DTF * (v1 + bb.y);
                    } else if constexpr (MODE == MODE_RELU_G) {
                        float2 bb = *(const float2*)(bias + c);
                        v0 += bb.x; v1 += bb.y;
                        v0 = v0 > 0.f ? v0 : 0.f; v1 = v1 > 0.f ? v1 : 0.f;
                    } else if constexpr (MODE == MODE_TANH2_G) {
                        float2 b1 = *(const float2*)(bias + c);
                        float2 b2 = *(const float2*)(bias2 + c);
                        float2 hh2 = *(const float2*)(Cin + (size_t)row * NOUT + c);
                        v0 = tanhf(v0 + hh2.x + b1.x + b2.x);
                        v1 = tanhf(v1 + hh2.y + b1.y + b2.y);
                    }
                    if constexpr (MODE == MODE_EULER || MODE == MODE_STORE || MODE == MODE_TANH2_G) {
                        *(float2*)(Cout + (size_t)row * NOUT + c) = make_float2(v0, v1);
                    }
                    if constexpr (MODE != MODE_STORE) {
                        __nv_bfloat16 h0 = __float2bfloat16(v0);
                        __nv_bfloat16 h1 = __float2bfloat16(v1);
                        __nv_bfloat16 l0 = __float2bfloat16(v0 - __bfloat162float(h0));
                        __nv_bfloat16 l1 = __float2bfloat16(v1 - __bfloat162float(h1));
                        union { __nv_bfloat16 b[2]; uint32_t u; } H, L;
                        H.b[0] = h0; H.b[1] = h1; L.b[0] = l0; L.b[1] = l1;
                        *(uint32_t*)(Ohi + (size_t)row * NOUT + c) = H.u;
                        *(uint32_t*)(Olo + (size_t)row * NOUT + c) = L.u;
                    }
                }
            }
        }
    }

    if constexpr (MODE == MODE_LOSS) {
#pragma unroll
        for (int o = 16; o > 0; o >>= 1) {
            lsum += __shfl_xor_sync(0xFFFFFFFFu, lsum, o);
            msum += __shfl_xor_sync(0xFFFFFFFFu, msum, o);
        }
        if (lid == 0) { redL[wid] = lsum; redM[wid] = msum; }
        __syncthreads();
        if (tid == 0) {
            float L = 0.f, Mt = 0.f;
#pragma unroll
            for (int i = 0; i < 8; i++) { L += redL[i]; Mt += redM[i]; }
            atomicAdd(&g_loss, (double)L);
            atomicAdd(&g_totm, (double)Mt);
        }
    }
}

// ------------------------------------------------------------------
// Small kernels
// ------------------------------------------------------------------
__global__ void init_kernel()
{
    size_t i = (size_t)blockIdx.x * blockDim.x + threadIdx.x;   // over n/4
    ((float4*)g_h)[i] = make_float4(0.f, 0.f, 0.f, 0.f);
    ((uint64_t*)g_h_hi)[i] = 0ull;
    ((uint64_t*)g_h_lo)[i] = 0ull;
    if (i == 0) { g_loss = 0.0; g_totm = 0.0; }
}

__global__ void conv_kernel(const float* __restrict__ src,
                            __nv_bfloat16* __restrict__ hi,
                            __nv_bfloat16* __restrict__ lo, int n4)
{
    int i = blockIdx.x * blockDim.x + threadIdx.x;
    if (i >= n4) return;
    float4 s = ((const float4*)src)[i];
    union { __nv_bfloat16 b[4]; uint64_t u; } H, L;
    const float* sp = &s.x;
#pragma unroll
    for (int j = 0; j < 4; j++) {
        __nv_bfloat16 hb = __float2bfloat16(sp[j]);
        H.b[j] = hb;
        L.b[j] = __float2bfloat16(sp[j] - __bfloat162float(hb));
    }
    ((uint64_t*)hi)[i] = H.u;
    ((uint64_t*)lo)[i] = L.u;
}

__global__ void scatter_kernel(const int* __restrict__ idx)
{
    int r = blockIdx.x;                 // 0..EOBS-1
    int t = threadIdx.x;                // 0..127
    int dst = idx[r];
    ((float4*)(g_h + (size_t)dst * HID))[t] = ((const float4*)(g_hn + (size_t)r * HID))[t];
    if (t < 64) {
        ((uint4*)(g_h_hi + (size_t)dst * HID))[t] = ((const uint4*)(g_hn_hi + (size_t)r * HID))[t];
    } else {
        ((uint4*)(g_h_lo + (size_t)dst * HID))[t - 64] = ((const uint4*)(g_hn_lo + (size_t)r * HID))[t - 64];
    }
}

__global__ void final_kernel(float* __restrict__ out)
{
    out[0] = (float)g_loss;
    out[1] = (float)(g_loss / g_totm);
}

// ------------------------------------------------------------------
// Launch
// ------------------------------------------------------------------
extern "C" void kernel_launch(void* const* d_in, const int* in_sizes, int n_in,
                              void* d_out, int out_size)
{
    const float* X    = (const float*)d_in[0];
    const float* Mm   = (const float*)d_in[1];
    const int*   bidx = (const int*)  d_in[2];
    const float* W_ih = (const float*)d_in[3];
    const float* b_ih = (const float*)d_in[4];
    const float* W_hh = (const float*)d_in[5];
    const float* b_hh = (const float*)d_in[6];
    const float* Wo1  = (const float*)d_in[7];
    const float* bo1  = (const float*)d_in[8];
    const float* Wo2  = (const float*)d_in[9];
    const float* bo2  = (const float*)d_in[10];
    const float* Wp1  = (const float*)d_in[11];
    const float* bp1  = (const float*)d_in[12];
    const float* Wp2  = (const float*)d_in[13];
    const float* bp2  = (const float*)d_in[14];

    float *h, *hn;
    __nv_bfloat16 *h_hi, *h_lo, *t_hi, *t_lo, *p1_hi, *p1_lo, *hn_hi, *hn_lo, *X_hi, *X_lo;
    __nv_bfloat16 *Wih_hi, *Wih_lo, *Whh_hi, *Whh_lo, *Wo1_hi, *Wo1_lo, *Wo2_hi, *Wo2_lo,
                  *Wp1_hi, *Wp1_lo, *Wp2_hi, *Wp2_lo;
    cudaGetSymbolAddress((void**)&h,     g_h);
    cudaGetSymbolAddress((void**)&hn,    g_hn);
    cudaGetSymbolAddress((void**)&h_hi,  g_h_hi);   cudaGetSymbolAddress((void**)&h_lo,  g_h_lo);
    cudaGetSymbolAddress((void**)&t_hi,  g_t_hi);   cudaGetSymbolAddress((void**)&t_lo,  g_t_lo);
    cudaGetSymbolAddress((void**)&p1_hi, g_p1_hi);  cudaGetSymbolAddress((void**)&p1_lo, g_p1_lo);
    cudaGetSymbolAddress((void**)&hn_hi, g_hn_hi);  cudaGetSymbolAddress((void**)&hn_lo, g_hn_lo);
    cudaGetSymbolAddress((void**)&X_hi,  g_X_hi);   cudaGetSymbolAddress((void**)&X_lo,  g_X_lo);
    cudaGetSymbolAddress((void**)&Wih_hi, g_Wih_hi); cudaGetSymbolAddress((void**)&Wih_lo, g_Wih_lo);
    cudaGetSymbolAddress((void**)&Whh_hi, g_Whh_hi); cudaGetSymbolAddress((void**)&Whh_lo, g_Whh_lo);
    cudaGetSymbolAddress((void**)&Wo1_hi, g_Wo1_hi); cudaGetSymbolAddress((void**)&Wo1_lo, g_Wo1_lo);
    cudaGetSymbolAddress((void**)&Wo2_hi, g_Wo2_hi); cudaGetSymbolAddress((void**)&Wo2_lo, g_Wo2_lo);
    cudaGetSymbolAddress((void**)&Wp1_hi, g_Wp1_hi); cudaGetSymbolAddress((void**)&Wp1_lo, g_Wp1_lo);
    cudaGetSymbolAddress((void**)&Wp2_hi, g_Wp2_hi); cudaGetSymbolAddress((void**)&Wp2_lo, g_Wp2_lo);

    cudaFuncSetAttribute(mma_gemm<MODE_TANH,   HID, HID>, cudaFuncAttributeMaxDynamicSharedMemorySize, SMEM_DYN);
    cudaFuncSetAttribute(mma_gemm<MODE_EULER,  HID, HID>, cudaFuncAttributeMaxDynamicSharedMemorySize, SMEM_DYN);
    cudaFuncSetAttribute(mma_gemm<MODE_RELU_G, HID, HID>, cudaFuncAttributeMaxDynamicSharedMemorySize, SMEM_DYN);
    cudaFuncSetAttribute(mma_gemm<MODE_LOSS,   HID, DIN>, cudaFuncAttributeMaxDynamicSharedMemorySize, SMEM_DYN);
    cudaFuncSetAttribute(mma_gemm<MODE_STORE,  DIN, HID>, cudaFuncAttributeMaxDynamicSharedMemorySize, SMEM_DYN);
    cudaFuncSetAttribute(mma_gemm<MODE_TANH2_G,HID, HID>, cudaFuncAttributeMaxDynamicSharedMemorySize, SMEM_DYN);

    init_kernel<<<(NSAMP * HID / 4) / 256, 256>>>();

    auto conv = [&](const float* s, __nv_bfloat16* hi, __nv_bfloat16* lo, int n) {
        conv_kernel<<<(n / 4 + 255) / 256, 256>>>(s, hi, lo, n / 4);
    };
    conv(X,    X_hi,  X_lo,  KOBS * EOBS * DIN);
    conv(W_ih, Wih_hi, Wih_lo, HID * DIN);
    conv(W_hh, Whh_hi, Whh_lo, HID * HID);
    conv(Wo1,  Wo1_hi, Wo1_lo, HID * HID);
    conv(Wo2,  Wo2_hi, Wo2_lo, HID * HID);
    conv(Wp1,  Wp1_hi, Wp1_lo, HID * HID);
    conv(Wp2,  Wp2_hi, Wp2_lo, DIN * HID);

    const dim3 gEuler(HID / 128, NSAMP / 128);  // (4, 128)
    const dim3 gObs  (HID / 128, EOBS  / 128);  // (4, 32)
    const dim3 gLoss (DIN / 128, EOBS  / 128);  // (1, 32)

    for (int s = 0; s < KOBS; s++) {
        const float* Xs = X  + (size_t)s * EOBS * DIN;
        const float* Ms = Mm + (size_t)s * EOBS * DIN;
        const int*   is = bidx + (size_t)s * EOBS;
        const __nv_bfloat16* Xhs = X_hi + (size_t)s * EOBS * DIN;
        const __nv_bfloat16* Xls = X_lo + (size_t)s * EOBS * DIN;

        for (int e = 0; e < 2; e++) {
            mma_gemm<MODE_TANH, HID, HID><<<gEuler, 256, SMEM_DYN>>>(
                h_hi, h_lo, Wo1_hi, Wo1_lo, bo1, nullptr,
                nullptr, nullptr, t_hi, t_lo, nullptr, nullptr, nullptr);
            mma_gemm<MODE_EULER, HID, HID><<<gEuler, 256, SMEM_DYN>>>(
                t_hi, t_lo, Wo2_hi, Wo2_lo, bo2, nullptr,
                h, h, h_hi, h_lo, nullptr, nullptr, nullptr);
        }
        mma_gemm<MODE_RELU_G, HID, HID><<<gObs, 256, SMEM_DYN>>>(
            h_hi, h_lo, Wp1_hi, Wp1_lo, bp1, nullptr,
            nullptr, nullptr, p1_hi, p1_lo, is, nullptr, nullptr);
        mma_gemm<MODE_LOSS, HID, DIN><<<gLoss, 256, SMEM_DYN>>>(
            p1_hi, p1_lo, Wp2_hi, Wp2_lo, bp2, nullptr,
            nullptr, nullptr, nullptr, nullptr, nullptr, Xs, Ms);
        mma_gemm<MODE_STORE, DIN, HID><<<gObs, 256, SMEM_DYN>>>(
            Xhs, Xls, Wih_hi, Wih_lo, nullptr, nullptr,
            nullptr, hn, nullptr, nullptr, nullptr, nullptr, nullptr);
        mma_gemm<MODE_TANH2_G, HID, HID><<<gObs, 256, SMEM_DYN>>>(
            h_hi, h_lo, Whh_hi, Whh_lo, b_ih, b_hh,
            hn, hn, hn_hi, hn_lo, is, nullptr, nullptr);
        scatter_kernel<<<EOBS, 128>>>(is);
    }
    // prop_to_end Euler steps are output-invariant -> skipped.

    final_kernel<<<1, 1>>>((float*)d_out);
}

// round 4
// speedup vs baseline: 3.1995x; 1.4533x over previous
#include <cuda_runtime.h>
#include <cuda_fp16.h>
#include <cstdint>
#include <cstddef>

#define NSAMP 16384
#define HID   512
#define DIN   128
#define EOBS  4096
#define KOBS  40
#define DTF   0.05f

#define MODE_TANH    0
#define MODE_EULER   1
#define MODE_RELU_G  2
#define MODE_RNN     3
#define MODE_LOSS    5

// ------------------------------------------------------------------
// Device scratch (no allocations allowed)
// ------------------------------------------------------------------
__device__ __half g_h_hi[(size_t)NSAMP*HID];
__device__ __half g_h_lo[(size_t)NSAMP*HID];
__device__ __half g_t_hi[(size_t)NSAMP*HID];
__device__ __half g_t_lo[(size_t)NSAMP*HID];
__device__ __half g_p1_hi[(size_t)EOBS*HID];
__device__ __half g_p1_lo[(size_t)EOBS*HID];
__device__ __half g_hn_hi[(size_t)EOBS*HID];
__device__ __half g_hn_lo[(size_t)EOBS*HID];
__device__ __half g_X_hi[(size_t)KOBS*EOBS*DIN];
__device__ __half g_X_lo[(size_t)KOBS*EOBS*DIN];

__device__ __half g_Wih_h[HID*DIN];
__device__ __half g_Whh_h[HID*HID];
__device__ __half g_Wo1_h[HID*HID];
__device__ __half g_Wo2_h[HID*HID];
__device__ __half g_Wp1_h[HID*HID];
__device__ __half g_Wp2_h[DIN*HID];

__device__ double g_loss;
__device__ double g_totm;

// ------------------------------------------------------------------
// PTX helpers (portable sm_80+)
// ------------------------------------------------------------------
__device__ __forceinline__ uint32_t smem_u32(const void* p) {
    uint32_t a;
    asm("{ .reg .u64 t; cvta.to.shared.u64 t, %1; cvt.u32.u64 %0, t; }" : "=r"(a) : "l"(p));
    return a;
}
__device__ __forceinline__ void cp16(uint32_t dst, const void* src) {
    asm volatile("cp.async.cg.shared.global [%0], [%1], 16;" :: "r"(dst), "l"(src) : "memory");
}
__device__ __forceinline__ void cp_commit() {
    asm volatile("cp.async.commit_group;" ::: "memory");
}
template<int N>
__device__ __forceinline__ void cp_wait() {
    asm volatile("cp.async.wait_group %0;" :: "n"(N) : "memory");
}
__device__ __forceinline__ void ldm4(uint32_t* r, uint32_t addr) {
    asm volatile("ldmatrix.sync.aligned.m8n8.x4.shared.b16 {%0,%1,%2,%3}, [%4];"
                 : "=r"(r[0]), "=r"(r[1]), "=r"(r[2]), "=r"(r[3]) : "r"(addr));
}
__device__ __forceinline__ void mma16816(float* d, const uint32_t* a, const uint32_t* b) {
    asm volatile(
        "mma.sync.aligned.m16n8k16.row.col.f32.f16.f16.f32 "
        "{%0,%1,%2,%3}, {%4,%5,%6,%7}, {%8,%9}, {%0,%1,%2,%3};"
        : "+f"(d[0]), "+f"(d[1]), "+f"(d[2]), "+f"(d[3])
        : "r"(a[0]), "r"(a[1]), "r"(a[2]), "r"(a[3]), "r"(b[0]), "r"(b[1]));
}

// SMEM plan: [pad ≤1024][2 stages × 3 mats × 16KB][ctrl 1KB]
#define TILE_BYTES   16384
#define STAGE_BYTES  49152
#define SMEM_DYN     (2*STAGE_BYTES + 1024 + 1024)

// ------------------------------------------------------------------
// Tensor-core GEMM: C[M,NOUT] = epi( A[M,K] @ W[NOUT,K]^T )
// A as fp16 hi/lo (2-MMA exact-A), W single fp16.
// CTA tile 128x128, 8 warps (4 row x 2 col), warp tile 32x64.
// MODE_RNN: K=640 concatenation  [X(128) | h_gathered(512)] @ [Wih | Whh]^T
// ------------------------------------------------------------------
template<int MODE, int KDIM, int NOUT>
__global__ __launch_bounds__(256, 2)
void mma_gemm(const __half* __restrict__ Ah,  const __half* __restrict__ Al,
              const __half* __restrict__ Bh,
              const __half* __restrict__ A2h, const __half* __restrict__ A2l,
              const __half* __restrict__ B2h,
              const float* __restrict__ bias, const float* __restrict__ bias2,
              const __half* __restrict__ Cin_hi, const __half* __restrict__ Cin_lo,
              __half* __restrict__ Ohi, __half* __restrict__ Olo,
              const int* __restrict__ gidx,
              const float* __restrict__ Xo, const float* __restrict__ Mo)
{
    constexpr int  NC     = KDIM / 64;
    constexpr bool GATHER = (MODE == MODE_RELU_G || MODE == MODE_RNN);

    extern __shared__ char smraw[];
    const uint32_t sbase = smem_u32(smraw);
    const uint32_t tbase = (sbase + 1023u) & ~1023u;
    char* ctrlp = smraw + (tbase - sbase) + 2 * STAGE_BYTES;
    int*   sIdx = (int*)ctrlp;            // 128 ints
    float* redL = (float*)(ctrlp + 512);  // 8 floats
    float* redM = (float*)(ctrlp + 544);  // 8 floats

    const int tid = threadIdx.x, wid = tid >> 5, lid = tid & 31;
    const int rowbase = blockIdx.y * 128;
    const int colbase = blockIdx.x * 128;
    const int wr = wid & 3, wc = wid >> 2;

    if (GATHER) {
        if (tid < 128) sIdx[tid] = gidx[rowbase + tid];
        __syncthreads();
    }

    // ---- async chunk loader: 3 mats × 128 rows × 128B, SW128-swizzled ----
    auto load_chunk = [&](int kc, int stage) {
        const uint32_t sb = tbase + (uint32_t)stage * STAGE_BYTES;
#pragma unroll
        for (int u = 0; u < 12; u++) {
            const int mat = u >> 2;                  // 0:Ah 1:Al 2:Bh
            const int rem = (u & 3) * 256 + tid;
            const int row = rem >> 3;
            const int un  = rem & 7;
            const __half* src;
            if constexpr (MODE == MODE_RNN) {
                if (mat < 2) {
                    if (kc < 2) src = (mat == 0 ? Ah : Al) + (size_t)(rowbase + row) * DIN + kc * 64 + un * 8;
                    else        src = (mat == 0 ? A2h : A2l) + (size_t)sIdx[row] * HID + (kc - 2) * 64 + un * 8;
                } else {
                    if (kc < 2) src = Bh  + (size_t)(colbase + row) * DIN + kc * 64 + un * 8;
                    else        src = B2h + (size_t)(colbase + row) * HID + (kc - 2) * 64 + un * 8;
                }
            } else {
                if (mat < 2) {
                    int rg = GATHER ? sIdx[row] : (rowbase + row);
                    src = (mat == 0 ? Ah : Al) + (size_t)rg * KDIM + kc * 64 + un * 8;
                } else {
                    src = Bh + (size_t)(colbase + row) * KDIM + kc * 64 + un * 8;
                }
            }
            uint32_t off = (uint32_t)(row * 128 + un * 16);
            off ^= (off >> 3) & 0x70;
            cp16(sb + (uint32_t)mat * TILE_BYTES + off, src);
        }
    };

    float acc[2][8][4];
#pragma unroll
    for (int i = 0; i < 2; i++)
#pragma unroll
        for (int j = 0; j < 8; j++)
#pragma unroll
            for (int q = 0; q < 4; q++) acc[i][j][q] = 0.f;

    // ---- compute one 64-wide K chunk from a stage ----
    auto compute = [&](int stage) {
        const uint32_t sb = tbase + (uint32_t)stage * STAGE_BYTES;
#pragma unroll
        for (int k16 = 0; k16 < 4; k16++) {
            uint32_t ah[2][4], al[2][4];
#pragma unroll
            for (int mi = 0; mi < 2; mi++) {
                uint32_t off = (uint32_t)((wr * 32 + mi * 16 + (lid & 15)) * 128
                                          + k16 * 32 + (lid >> 4) * 16);
                off ^= (off >> 3) & 0x70;
                ldm4(ah[mi], sb + off);
                ldm4(al[mi], sb + TILE_BYTES + off);
            }
            uint32_t bh[4][4];
#pragma unroll
            for (int nb = 0; nb < 4; nb++) {
                uint32_t off = (uint32_t)((wc * 64 + nb * 16 + (lid & 7) + ((lid >> 4) & 1) * 8) * 128
                                          + k16 * 32 + ((lid >> 3) & 1) * 16);
                off ^= (off >> 3) & 0x70;
                ldm4(bh[nb], sb + 2 * TILE_BYTES + off);
            }
#pragma unroll
            for (int mi = 0; mi < 2; mi++)
#pragma unroll
                for (int na = 0; na < 8; na++) {
                    const uint32_t* B2 = &bh[na >> 1][(na & 1) * 2];
                    mma16816(acc[mi][na], ah[mi], B2);
                    mma16816(acc[mi][na], al[mi], B2);
                }
        }
    };

    // ---- pipelined mainloop ----
    load_chunk(0, 0); cp_commit();
#pragma unroll 1
    for (int c = 0; c < NC; c++) {
        if (c + 1 < NC) { load_chunk(c + 1, (c + 1) & 1); cp_commit(); cp_wait<1>(); }
        else            { cp_wait<0>(); }
        __syncthreads();
        compute(c & 1);
        __syncthreads();
    }

    // ---- epilogue from register accumulators ----
    float lsum = 0.f, msum = 0.f;
#pragma unroll
    for (int mi = 0; mi < 2; mi++) {
#pragma unroll
        for (int hh = 0; hh < 2; hh++) {
            const int row = rowbase + wr * 32 + mi * 16 + (lid >> 2) + hh * 8;
#pragma unroll
            for (int na = 0; na < 8; na++) {
                const int c = colbase + wc * 64 + na * 8 + (lid & 3) * 2;
                float v0 = acc[mi][na][hh * 2 + 0];
                float v1 = acc[mi][na][hh * 2 + 1];
                if constexpr (MODE == MODE_LOSS) {
                    float2 bb = *(const float2*)(bias + c);
                    float2 xx = *(const float2*)(Xo + (size_t)row * NOUT + c);
                    float2 mm = *(const float2*)(Mo + (size_t)row * NOUT + c);
                    lsum += fabsf(xx.x - (v0 + bb.x)) * mm.x + fabsf(xx.y - (v1 + bb.y)) * mm.y;
                    msum += mm.x + mm.y;
                } else {
                    if constexpr (MODE == MODE_TANH) {
                        float2 bb = *(const float2*)(bias + c);
                        v0 = tanhf(v0 + bb.x); v1 = tanhf(v1 + bb.y);
                    } else if constexpr (MODE == MODE_EULER) {
                        float2 bb = *(const float2*)(bias + c);
                        float2 chv = __half22float2(*(const __half2*)(Cin_hi + (size_t)row * NOUT + c));
                        float2 clv = __half22float2(*(const __half2*)(Cin_lo + (size_t)row * NOUT + c));
                        v0 = (chv.x + clv.x) + DTF * (v0 + bb.x);
                        v1 = (chv.y + clv.y) + DTF * (v1 + bb.y);
                    } else if constexpr (MODE == MODE_RELU_G) {
                        float2 bb = *(const float2*)(bias + c);
                        v0 += bb.x; v1 += bb.y;
                        v0 = v0 > 0.f ? v0 : 0.f; v1 = v1 > 0.f ? v1 : 0.f;
                    } else if constexpr (MODE == MODE_RNN) {
                        float2 b1 = *(const float2*)(bias + c);
                        float2 b2 = *(const float2*)(bias2 + c);
                        v0 = tanhf(v0 + b1.x + b2.x);
                        v1 = tanhf(v1 + b1.y + b2.y);
                    }
                    __half h0 = __float2half_rn(v0);
                    __half h1 = __float2half_rn(v1);
                    __half l0 = __float2half_rn(v0 - __half2float(h0));
                    __half l1 = __float2half_rn(v1 - __half2float(h1));
                    *(__half2*)(Ohi + (size_t)row * NOUT + c) = __halves2half2(h0, h1);
                    *(__half2*)(Olo + (size_t)row * NOUT + c) = __halves2half2(l0, l1);
                }
            }
        }
    }

    if constexpr (MODE == MODE_LOSS) {
#pragma unroll
        for (int o = 16; o > 0; o >>= 1) {
            lsum += __shfl_xor_sync(0xFFFFFFFFu, lsum, o);
            msum += __shfl_xor_sync(0xFFFFFFFFu, msum, o);
        }
        if (lid == 0) { redL[wid] = lsum; redM[wid] = msum; }
        __syncthreads();
        if (tid == 0) {
            float L = 0.f, Mt = 0.f;
#pragma unroll
            for (int i = 0; i < 8; i++) { L += redL[i]; Mt += redM[i]; }
            atomicAdd(&g_loss, (double)L);
            atomicAdd(&g_totm, (double)Mt);
        }
    }
}

// ------------------------------------------------------------------
// Small kernels
// ------------------------------------------------------------------
__global__ void init_kernel()
{
    size_t i = (size_t)blockIdx.x * blockDim.x + threadIdx.x;   // over NSAMP*HID/8
    ((uint4*)g_h_hi)[i] = make_uint4(0, 0, 0, 0);
    ((uint4*)g_h_lo)[i] = make_uint4(0, 0, 0, 0);
    if (i == 0) { g_loss = 0.0; g_totm = 0.0; }
}

__global__ void conv_split_kernel(const float* __restrict__ src,
                                  __half* __restrict__ hi,
                                  __half* __restrict__ lo, int n4)
{
    int i = blockIdx.x * blockDim.x + threadIdx.x;
    if (i >= n4) return;
    float4 s = ((const float4*)src)[i];
    __half h0 = __float2half_rn(s.x), h1 = __float2half_rn(s.y),
           h2 = __float2half_rn(s.z), h3 = __float2half_rn(s.w);
    __half l0 = __float2half_rn(s.x - __half2float(h0));
    __half l1 = __float2half_rn(s.y - __half2float(h1));
    __half l2 = __float2half_rn(s.z - __half2float(h2));
    __half l3 = __float2half_rn(s.w - __half2float(h3));
    ((__half2*)hi)[i * 2]     = __halves2half2(h0, h1);
    ((__half2*)hi)[i * 2 + 1] = __halves2half2(h2, h3);
    ((__half2*)lo)[i * 2]     = __halves2half2(l0, l1);
    ((__half2*)lo)[i * 2 + 1] = __halves2half2(l2, l3);
}

__global__ void conv_hi_kernel(const float* __restrict__ src,
                               __half* __restrict__ hi, int n4)
{
    int i = blockIdx.x * blockDim.x + threadIdx.x;
    if (i >= n4) return;
    float4 s = ((const float4*)src)[i];
    ((__half2*)hi)[i * 2]     = __halves2half2(__float2half_rn(s.x), __float2half_rn(s.y));
    ((__half2*)hi)[i * 2 + 1] = __halves2half2(__float2half_rn(s.z), __float2half_rn(s.w));
}

__global__ void scatter_kernel(const int* __restrict__ idx)
{
    int r = blockIdx.x;                 // 0..EOBS-1
    int t = threadIdx.x;                // 0..127
    int dst = idx[r];
    if (t < 64) {
        ((uint4*)(g_h_hi + (size_t)dst * HID))[t] = ((const uint4*)(g_hn_hi + (size_t)r * HID))[t];
    } else {
        ((uint4*)(g_h_lo + (size_t)dst * HID))[t - 64] = ((const uint4*)(g_hn_lo + (size_t)r * HID))[t - 64];
    }
}

__global__ void final_kernel(float* __restrict__ out)
{
    out[0] = (float)g_loss;
    out[1] = (float)(g_loss / g_totm);
}

// ------------------------------------------------------------------
// Launch
// ------------------------------------------------------------------
extern "C" void kernel_launch(void* const* d_in, const int* in_sizes, int n_in,
                              void* d_out, int out_size)
{
    const float* X    = (const float*)d_in[0];
    const float* Mm   = (const float*)d_in[1];
    const int*   bidx = (const int*)  d_in[2];
    const float* W_ih = (const float*)d_in[3];
    const float* b_ih = (const float*)d_in[4];
    const float* W_hh = (const float*)d_in[5];
    const float* b_hh = (const float*)d_in[6];
    const float* Wo1  = (const float*)d_in[7];
    const float* bo1  = (const float*)d_in[8];
    const float* Wo2  = (const float*)d_in[9];
    const float* bo2  = (const float*)d_in[10];
    const float* Wp1  = (const float*)d_in[11];
    const float* bp1  = (const float*)d_in[12];
    const float* Wp2  = (const float*)d_in[13];
    const float* bp2  = (const float*)d_in[14];

    __half *h_hi, *h_lo, *t_hi, *t_lo, *p1_hi, *p1_lo, *hn_hi, *hn_lo, *X_hi, *X_lo;
    __half *Wih, *Whh, *Wo1h, *Wo2h, *Wp1h, *Wp2h;
    cudaGetSymbolAddress((void**)&h_hi,  g_h_hi);   cudaGetSymbolAddress((void**)&h_lo,  g_h_lo);
    cudaGetSymbolAddress((void**)&t_hi,  g_t_hi);   cudaGetSymbolAddress((void**)&t_lo,  g_t_lo);
    cudaGetSymbolAddress((void**)&p1_hi, g_p1_hi);  cudaGetSymbolAddress((void**)&p1_lo, g_p1_lo);
    cudaGetSymbolAddress((void**)&hn_hi, g_hn_hi);  cudaGetSymbolAddress((void**)&hn_lo, g_hn_lo);
    cudaGetSymbolAddress((void**)&X_hi,  g_X_hi);   cudaGetSymbolAddress((void**)&X_lo,  g_X_lo);
    cudaGetSymbolAddress((void**)&Wih,  g_Wih_h);
    cudaGetSymbolAddress((void**)&Whh,  g_Whh_h);
    cudaGetSymbolAddress((void**)&Wo1h, g_Wo1_h);
    cudaGetSymbolAddress((void**)&Wo2h, g_Wo2_h);
    cudaGetSymbolAddress((void**)&Wp1h, g_Wp1_h);
    cudaGetSymbolAddress((void**)&Wp2h, g_Wp2_h);

    cudaFuncSetAttribute(mma_gemm<MODE_TANH,   HID, HID>, cudaFuncAttributeMaxDynamicSharedMemorySize, SMEM_DYN);
    cudaFuncSetAttribute(mma_gemm<MODE_EULER,  HID, HID>, cudaFuncAttributeMaxDynamicSharedMemorySize, SMEM_DYN);
    cudaFuncSetAttribute(mma_gemm<MODE_RELU_G, HID, HID>, cudaFuncAttributeMaxDynamicSharedMemorySize, SMEM_DYN);
    cudaFuncSetAttribute(mma_gemm<MODE_LOSS,   HID, DIN>, cudaFuncAttributeMaxDynamicSharedMemorySize, SMEM_DYN);
    cudaFuncSetAttribute(mma_gemm<MODE_RNN,    640, HID>, cudaFuncAttributeMaxDynamicSharedMemorySize, SMEM_DYN);

    init_kernel<<<(NSAMP * HID / 8) / 256, 256>>>();

    conv_split_kernel<<<(KOBS*EOBS*DIN/4 + 255)/256, 256>>>(X, X_hi, X_lo, KOBS*EOBS*DIN/4);
    conv_hi_kernel<<<(HID*DIN/4 + 255)/256, 256>>>(W_ih, Wih,  HID*DIN/4);
    conv_hi_kernel<<<(HID*HID/4 + 255)/256, 256>>>(W_hh, Whh,  HID*HID/4);
    conv_hi_kernel<<<(HID*HID/4 + 255)/256, 256>>>(Wo1,  Wo1h, HID*HID/4);
    conv_hi_kernel<<<(HID*HID/4 + 255)/256, 256>>>(Wo2,  Wo2h, HID*HID/4);
    conv_hi_kernel<<<(HID*HID/4 + 255)/256, 256>>>(Wp1,  Wp1h, HID*HID/4);
    conv_hi_kernel<<<(DIN*HID/4 + 255)/256, 256>>>(Wp2,  Wp2h, DIN*HID/4);

    const dim3 gEuler(HID / 128, NSAMP / 128);  // (4, 128)
    const dim3 gObs  (HID / 128, EOBS  / 128);  // (4, 32)
    const dim3 gLoss (DIN / 128, EOBS  / 128);  // (1, 32)

    for (int s = 0; s < KOBS; s++) {
        const float* Xs = X  + (size_t)s * EOBS * DIN;
        const float* Ms = Mm + (size_t)s * EOBS * DIN;
        const int*   is = bidx + (size_t)s * EOBS;
        const __half* Xhs = X_hi + (size_t)s * EOBS * DIN;
        const __half* Xls = X_lo + (size_t)s * EOBS * DIN;

        for (int e = 0; e < 2; e++) {
            // t = tanh(h @ Wo1^T + bo1)
            mma_gemm<MODE_TANH, HID, HID><<<gEuler, 256, SMEM_DYN>>>(
                h_hi, h_lo, Wo1h, nullptr, nullptr, nullptr,
                bo1, nullptr, nullptr, nullptr, t_hi, t_lo, nullptr, nullptr, nullptr);
            // h = (h_hi+h_lo) + DT*(t @ Wo2^T + bo2)
            mma_gemm<MODE_EULER, HID, HID><<<gEuler, 256, SMEM_DYN>>>(
                t_hi, t_lo, Wo2h, nullptr, nullptr, nullptr,
                bo2, nullptr, h_hi, h_lo, h_hi, h_lo, nullptr, nullptr, nullptr);
        }
        // p1 = relu(h[idx] @ Wp1^T + bp1)
        mma_gemm<MODE_RELU_G, HID, HID><<<gObs, 256, SMEM_DYN>>>(
            h_hi, h_lo, Wp1h, nullptr, nullptr, nullptr,
            bp1, nullptr, nullptr, nullptr, p1_hi, p1_lo, is, nullptr, nullptr);
        // loss += sum |X - (p1 @ Wp2^T + bp2)| * M ; totm += sum M
        mma_gemm<MODE_LOSS, HID, DIN><<<gLoss, 256, SMEM_DYN>>>(
            p1_hi, p1_lo, Wp2h, nullptr, nullptr, nullptr,
            bp2, nullptr, nullptr, nullptr, nullptr, nullptr, nullptr, Xs, Ms);
        // hn = tanh([X | h[idx]] @ [Wih | Whh]^T + b_ih + b_hh)   (K = 640)
        mma_gemm<MODE_RNN, 640, HID><<<gObs, 256, SMEM_DYN>>>(
            Xhs, Xls, Wih, h_hi, h_lo, Whh,
            b_ih, b_hh, nullptr, nullptr, hn_hi, hn_lo, is, nullptr, nullptr);
        // h[idx] = hn
        scatter_kernel<<<EOBS, 128>>>(is);
    }
    // prop_to_end Euler steps are output-invariant -> skipped.

    final_kernel<<<1, 1>>>((float*)d_out);
}

// round 6
// speedup vs baseline: 5.0150x; 1.5674x over previous
#include <cuda_runtime.h>
#include <cuda_fp16.h>
#include <cstdint>
#include <cstddef>

#define NSAMP 16384
#define HID   512
#define DIN   128
#define EOBS  4096
#define KOBS  40
#define DTF   0.05f

#define MODE_TANH    0
#define MODE_EULER   1
#define MODE_RELU_G  2
#define MODE_RNN     3
#define MODE_LOSS    5

// ------------------------------------------------------------------
// Device scratch (no allocations allowed)
// ------------------------------------------------------------------
__device__ __half g_h_hi[(size_t)NSAMP*HID];   // state hi
__device__ __half g_h_lo[(size_t)NSAMP*HID];   // state lo (precision carrier)
__device__ __half g_t_hi[(size_t)NSAMP*HID];
__device__ __half g_p1_hi[(size_t)EOBS*HID];
__device__ __half g_hn_hi[(size_t)EOBS*HID];
__device__ __half g_hn_lo[(size_t)EOBS*HID];
__device__ __half g_X_hi[(size_t)KOBS*EOBS*DIN];

__device__ __half g_Wih_h[HID*DIN];
__device__ __half g_Whh_h[HID*HID];
__device__ __half g_Wo1_h[HID*HID];
__device__ __half g_Wo2_h[HID*HID];
__device__ __half g_Wp1_h[HID*HID];
__device__ __half g_Wp2_h[DIN*HID];

__device__ double g_loss;
__device__ double g_totm;

// ------------------------------------------------------------------
// PTX helpers (portable sm_80+)
// ------------------------------------------------------------------
__device__ __forceinline__ uint32_t smem_u32(const void* p) {
    uint32_t a;
    asm("{ .reg .u64 t; cvta.to.shared.u64 t, %1; cvt.u32.u64 %0, t; }" : "=r"(a) : "l"(p));
    return a;
}
__device__ __forceinline__ void cp16(uint32_t dst, const void* src) {
    asm volatile("cp.async.cg.shared.global [%0], [%1], 16;" :: "r"(dst), "l"(src) : "memory");
}
__device__ __forceinline__ void cp_commit() {
    asm volatile("cp.async.commit_group;" ::: "memory");
}
template<int N>
__device__ __forceinline__ void cp_wait() {
    asm volatile("cp.async.wait_group %0;" :: "n"(N) : "memory");
}
__device__ __forceinline__ void ldm4(uint32_t* r, uint32_t addr) {
    asm volatile("ldmatrix.sync.aligned.m8n8.x4.shared.b16 {%0,%1,%2,%3}, [%4];"
                 : "=r"(r[0]), "=r"(r[1]), "=r"(r[2]), "=r"(r[3]) : "r"(addr));
}
__device__ __forceinline__ void mma16816(float* d, const uint32_t* a, const uint32_t* b) {
    asm volatile(
        "mma.sync.aligned.m16n8k16.row.col.f32.f16.f16.f32 "
        "{%0,%1,%2,%3}, {%4,%5,%6,%7}, {%8,%9}, {%0,%1,%2,%3};"
        : "+f"(d[0]), "+f"(d[1]), "+f"(d[2]), "+f"(d[3])
        : "r"(a[0]), "r"(a[1]), "r"(a[2]), "r"(a[3]), "r"(b[0]), "r"(b[1]));
}

// SMEM plan: [pad ≤1024][3 stages × 2 mats × 16KB][ctrl 1KB]
#define TILE_BYTES   16384
#define STAGE_BYTES  32768
#define NSTAGE       3
#define SMEM_DYN     (NSTAGE*STAGE_BYTES + 1024 + 1024)

// ------------------------------------------------------------------
// Tensor-core GEMM: C[M,NOUT] = epi( A[M,K] @ W[NOUT,K]^T )
// A fp16 (single), W fp16 (single) -> 1 MMA per product.
// CTA tile 128x128, 8 warps (4 row x 2 col), warp tile 32x64.
// MODE_RNN: K=640 concatenation  [X(128) | h_gathered(512)] @ [Wih | Whh]^T
// ------------------------------------------------------------------
template<int MODE, int KDIM, int NOUT>
__global__ __launch_bounds__(256, 2)
void mma_gemm(const __half* __restrict__ Ah,  const __half* __restrict__ Bh,
              const __half* __restrict__ A2h, const __half* __restrict__ B2h,
              const float* __restrict__ bias, const float* __restrict__ bias2,
              const __half* __restrict__ Cin_hi, const __half* __restrict__ Cin_lo,
              __half* __restrict__ Ohi, __half* __restrict__ Olo,
              const int* __restrict__ gidx,
              const float* __restrict__ Xo, const float* __restrict__ Mo)
{
    constexpr int  NC     = KDIM / 64;
    constexpr bool GATHER = (MODE == MODE_RELU_G || MODE == MODE_RNN);

    extern __shared__ char smraw[];
    const uint32_t sbase = smem_u32(smraw);
    const uint32_t tbase = (sbase + 1023u) & ~1023u;
    char* ctrlp = smraw + (tbase - sbase) + NSTAGE * STAGE_BYTES;
    int*   sIdx = (int*)ctrlp;            // 128 ints
    float* redL = (float*)(ctrlp + 512);  // 8 floats
    float* redM = (float*)(ctrlp + 544);  // 8 floats

    const int tid = threadIdx.x, wid = tid >> 5, lid = tid & 31;
    const int rowbase = blockIdx.y * 128;
    const int colbase = blockIdx.x * 128;
    const int wr = wid & 3, wc = wid >> 2;

    if (GATHER) {
        if (tid < 128) sIdx[tid] = gidx[rowbase + tid];
        __syncthreads();
    }

    // ---- async chunk loader: 2 mats × 128 rows × 128B, SW128-swizzled ----
    auto load_chunk = [&](int kc, int stage) {
        const uint32_t sb = tbase + (uint32_t)stage * STAGE_BYTES;
#pragma unroll
        for (int u = 0; u < 8; u++) {
            const int mat = u >> 2;                  // 0:A 1:B
            const int rem = (u & 3) * 256 + tid;
            const int row = rem >> 3;
            const int un  = rem & 7;
            const __half* src;
            if constexpr (MODE == MODE_RNN) {
                if (mat == 0) {
                    if (kc < 2) src = Ah  + (size_t)(rowbase + row) * DIN + kc * 64 + un * 8;
                    else        src = A2h + (size_t)sIdx[row] * HID + (kc - 2) * 64 + un * 8;
                } else {
                    if (kc < 2) src = Bh  + (size_t)(colbase + row) * DIN + kc * 64 + un * 8;
                    else        src = B2h + (size_t)(colbase + row) * HID + (kc - 2) * 64 + un * 8;
                }
            } else {
                if (mat == 0) {
                    int rg = GATHER ? sIdx[row] : (rowbase + row);
                    src = Ah + (size_t)rg * KDIM + kc * 64 + un * 8;
                } else {
                    src = Bh + (size_t)(colbase + row) * KDIM + kc * 64 + un * 8;
                }
            }
            uint32_t off = (uint32_t)(row * 128 + un * 16);
            off ^= (off >> 3) & 0x70;
            cp16(sb + (uint32_t)mat * TILE_BYTES + off, src);
        }
    };

    float acc[2][8][4];
#pragma unroll
    for (int i = 0; i < 2; i++)
#pragma unroll
        for (int j = 0; j < 8; j++)
#pragma unroll
            for (int q = 0; q < 4; q++) acc[i][j][q] = 0.f;

    // ---- compute one 64-wide K chunk from a stage ----
    auto compute = [&](int stage) {
        const uint32_t sb = tbase + (uint32_t)stage * STAGE_BYTES;
#pragma unroll
        for (int k16 = 0; k16 < 4; k16++) {
            uint32_t ah[2][4];
#pragma unroll
            for (int mi = 0; mi < 2; mi++) {
                uint32_t off = (uint32_t)((wr * 32 + mi * 16 + (lid & 15)) * 128
                                          + k16 * 32 + (lid >> 4) * 16);
                off ^= (off >> 3) & 0x70;
                ldm4(ah[mi], sb + off);
            }
            uint32_t bh[4][4];
#pragma unroll
            for (int nb = 0; nb < 4; nb++) {
                uint32_t off = (uint32_t)((wc * 64 + nb * 16 + (lid & 7) + ((lid >> 4) & 1) * 8) * 128
                                          + k16 * 32 + ((lid >> 3) & 1) * 16);
                off ^= (off >> 3) & 0x70;
                ldm4(bh[nb], sb + 2 * TILE_BYTES + off - TILE_BYTES);  // mat1 base
            }
#pragma unroll
            for (int mi = 0; mi < 2; mi++)
#pragma unroll
                for (int na = 0; na < 8; na++) {
                    const uint32_t* B2 = &bh[na >> 1][(na & 1) * 2];
                    mma16816(acc[mi][na], ah[mi], B2);
                }
        }
    };

    // ---- 3-stage pipelined mainloop ----
    load_chunk(0, 0); cp_commit();
    if (NC > 1) { load_chunk(1, 1); cp_commit(); }
#pragma unroll 1
    for (int c = 0; c < NC; c++) {
        if (c + 2 < NC) { load_chunk(c + 2, (c + 2) % NSTAGE); cp_commit(); cp_wait<2>(); }
        else if (c + 1 < NC) { cp_wait<1>(); }
        else { cp_wait<0>(); }
        __syncthreads();
        compute(c % NSTAGE);
        __syncthreads();
    }

    // ---- epilogue from register accumulators ----
    float lsum = 0.f, msum = 0.f;
#pragma unroll
    for (int mi = 0; mi < 2; mi++) {
#pragma unroll
        for (int hh = 0; hh < 2; hh++) {
            const int row = rowbase + wr * 32 + mi * 16 + (lid >> 2) + hh * 8;
#pragma unroll
            for (int na = 0; na < 8; na++) {
                const int c = colbase + wc * 64 + na * 8 + (lid & 3) * 2;
                float v0 = acc[mi][na][hh * 2 + 0];
                float v1 = acc[mi][na][hh * 2 + 1];
                if constexpr (MODE == MODE_LOSS) {
                    float2 bb = *(const float2*)(bias + c);
                    float2 xx = *(const float2*)(Xo + (size_t)row * NOUT + c);
                    float2 mm = *(const float2*)(Mo + (size_t)row * NOUT + c);
                    lsum += fabsf(xx.x - (v0 + bb.x)) * mm.x + fabsf(xx.y - (v1 + bb.y)) * mm.y;
                    msum += mm.x + mm.y;
                } else {
                    if constexpr (MODE == MODE_TANH) {
                        float2 bb = *(const float2*)(bias + c);
                        v0 = tanhf(v0 + bb.x); v1 = tanhf(v1 + bb.y);
                    } else if constexpr (MODE == MODE_EULER) {
                        float2 bb = *(const float2*)(bias + c);
                        float2 chv = __half22float2(*(const __half2*)(Cin_hi + (size_t)row * NOUT + c));
                        float2 clv = __half22float2(*(const __half2*)(Cin_lo + (size_t)row * NOUT + c));
                        v0 = (chv.x + clv.x) + DTF * (v0 + bb.x);
                        v1 = (chv.y + clv.y) + DTF * (v1 + bb.y);
                    } else if constexpr (MODE == MODE_RELU_G) {
                        float2 bb = *(const float2*)(bias + c);
                        v0 += bb.x; v1 += bb.y;
                        v0 = v0 > 0.f ? v0 : 0.f; v1 = v1 > 0.f ? v1 : 0.f;
                    } else if constexpr (MODE == MODE_RNN) {
                        float2 b1 = *(const float2*)(bias + c);
                        float2 b2 = *(const float2*)(bias2 + c);
                        v0 = tanhf(v0 + b1.x + b2.x);
                        v1 = tanhf(v1 + b1.y + b2.y);
                    }
                    __half h0 = __float2half_rn(v0);
                    __half h1 = __float2half_rn(v1);
                    *(__half2*)(Ohi + (size_t)row * NOUT + c) = __halves2half2(h0, h1);
                    if constexpr (MODE == MODE_EULER || MODE == MODE_RNN) {
                        __half l0 = __float2half_rn(v0 - __half2float(h0));
                        __half l1 = __float2half_rn(v1 - __half2float(h1));
                        *(__half2*)(Olo + (size_t)row * NOUT + c) = __halves2half2(l0, l1);
                    }
                }
            }
        }
    }

    if constexpr (MODE == MODE_LOSS) {
#pragma unroll
        for (int o = 16; o > 0; o >>= 1) {
            lsum += __shfl_xor_sync(0xFFFFFFFFu, lsum, o);
            msum += __shfl_xor_sync(0xFFFFFFFFu, msum, o);
        }
        if (lid == 0) { redL[wid] = lsum; redM[wid] = msum; }
        __syncthreads();
        if (tid == 0) {
            float L = 0.f, Mt = 0.f;
#pragma unroll
            for (int i = 0; i < 8; i++) { L += redL[i]; Mt += redM[i]; }
            atomicAdd(&g_loss, (double)L);
            atomicAdd(&g_totm, (double)Mt);
        }
    }
}

// ------------------------------------------------------------------
// Small kernels
// ------------------------------------------------------------------
__global__ void init_kernel()
{
    size_t i = (size_t)blockIdx.x * blockDim.x + threadIdx.x;   // over NSAMP*HID/8
    ((uint4*)g_h_hi)[i] = make_uint4(0, 0, 0, 0);
    ((uint4*)g_h_lo)[i] = make_uint4(0, 0, 0, 0);
    if (i == 0) { g_loss = 0.0; g_totm = 0.0; }
}

__global__ void conv_hi_kernel(const float* __restrict__ src,
                               __half* __restrict__ hi, int n4)
{
    int i = blockIdx.x * blockDim.x + threadIdx.x;
    if (i >= n4) return;
    float4 s = ((const float4*)src)[i];
    ((__half2*)hi)[i * 2]     = __halves2half2(__float2half_rn(s.x), __float2half_rn(s.y));
    ((__half2*)hi)[i * 2 + 1] = __halves2half2(__float2half_rn(s.z), __float2half_rn(s.w));
}

__global__ void scatter_kernel(const int* __restrict__ idx)
{
    int r = blockIdx.x;                 // 0..EOBS-1
    int t = threadIdx.x;                // 0..127
    int dst = idx[r];
    if (t < 64) {
        ((uint4*)(g_h_hi + (size_t)dst * HID))[t] = ((const uint4*)(g_hn_hi + (size_t)r * HID))[t];
    } else {
        ((uint4*)(g_h_lo + (size_t)dst * HID))[t - 64] = ((const uint4*)(g_hn_lo + (size_t)r * HID))[t - 64];
    }
}

__global__ void final_kernel(float* __restrict__ out)
{
    out[0] = (float)g_loss;
    out[1] = (float)(g_loss / g_totm);
}

// ------------------------------------------------------------------
// Launch
// ------------------------------------------------------------------
extern "C" void kernel_launch(void* const* d_in, const int* in_sizes, int n_in,
                              void* d_out, int out_size)
{
    const float* X    = (const float*)d_in[0];
    const float* Mm   = (const float*)d_in[1];
    const int*   bidx = (const int*)  d_in[2];
    const float* W_ih = (const float*)d_in[3];
    const float* b_ih = (const float*)d_in[4];
    const float* W_hh = (const float*)d_in[5];
    const float* b_hh = (const float*)d_in[6];
    const float* Wo1  = (const float*)d_in[7];
    const float* bo1  = (const float*)d_in[8];
    const float* Wo2  = (const float*)d_in[9];
    const float* bo2  = (const float*)d_in[10];
    const float* Wp1  = (const float*)d_in[11];
    const float* bp1  = (const float*)d_in[12];
    const float* Wp2  = (const float*)d_in[13];
    const float* bp2  = (const float*)d_in[14];

    __half *h_hi, *h_lo, *t_hi, *p1_hi, *hn_hi, *hn_lo, *X_hi;
    __half *Wih, *Whh, *Wo1h, *Wo2h, *Wp1h, *Wp2h;
    cudaGetSymbolAddress((void**)&h_hi,  g_h_hi);   cudaGetSymbolAddress((void**)&h_lo,  g_h_lo);
    cudaGetSymbolAddress((void**)&t_hi,  g_t_hi);
    cudaGetSymbolAddress((void**)&p1_hi, g_p1_hi);
    cudaGetSymbolAddress((void**)&hn_hi, g_hn_hi);  cudaGetSymbolAddress((void**)&hn_lo, g_hn_lo);
    cudaGetSymbolAddress((void**)&X_hi,  g_X_hi);
    cudaGetSymbolAddress((void**)&Wih,  g_Wih_h);
    cudaGetSymbolAddress((void**)&Whh,  g_Whh_h);
    cudaGetSymbolAddress((void**)&Wo1h, g_Wo1_h);
    cudaGetSymbolAddress((void**)&Wo2h, g_Wo2_h);
    cudaGetSymbolAddress((void**)&Wp1h, g_Wp1_h);
    cudaGetSymbolAddress((void**)&Wp2h, g_Wp2_h);

    cudaFuncSetAttribute(mma_gemm<MODE_TANH,   HID, HID>, cudaFuncAttributeMaxDynamicSharedMemorySize, SMEM_DYN);
    cudaFuncSetAttribute(mma_gemm<MODE_EULER,  HID, HID>, cudaFuncAttributeMaxDynamicSharedMemorySize, SMEM_DYN);
    cudaFuncSetAttribute(mma_gemm<MODE_RELU_G, HID, HID>, cudaFuncAttributeMaxDynamicSharedMemorySize, SMEM_DYN);
    cudaFuncSetAttribute(mma_gemm<MODE_LOSS,   HID, DIN>, cudaFuncAttributeMaxDynamicSharedMemorySize, SMEM_DYN);
    cudaFuncSetAttribute(mma_gemm<MODE_RNN,    640, HID>, cudaFuncAttributeMaxDynamicSharedMemorySize, SMEM_DYN);

    init_kernel<<<(NSAMP * HID / 8) / 256, 256>>>();

    conv_hi_kernel<<<(KOBS*EOBS*DIN/4 + 255)/256, 256>>>(X, X_hi, KOBS*EOBS*DIN/4);
    conv_hi_kernel<<<(HID*DIN/4 + 255)/256, 256>>>(W_ih, Wih,  HID*DIN/4);
    conv_hi_kernel<<<(HID*HID/4 + 255)/256, 256>>>(W_hh, Whh,  HID*HID/4);
    conv_hi_kernel<<<(HID*HID/4 + 255)/256, 256>>>(Wo1,  Wo1h, HID*HID/4);
    conv_hi_kernel<<<(HID*HID/4 + 255)/256, 256>>>(Wo2,  Wo2h, HID*HID/4);
    conv_hi_kernel<<<(HID*HID/4 + 255)/256, 256>>>(Wp1,  Wp1h, HID*HID/4);
    conv_hi_kernel<<<(DIN*HID/4 + 255)/256, 256>>>(Wp2,  Wp2h, DIN*HID/4);

    const dim3 gEuler(HID / 128, NSAMP / 128);  // (4, 128)
    const dim3 gObs  (HID / 128, EOBS  / 128);  // (4, 32)
    const dim3 gLoss (DIN / 128, EOBS  / 128);  // (1, 32)

    for (int s = 0; s < KOBS; s++) {
        const float* Xs = X  + (size_t)s * EOBS * DIN;
        const float* Ms = Mm + (size_t)s * EOBS * DIN;
        const int*   is = bidx + (size_t)s * EOBS;
        const __half* Xhs = X_hi + (size_t)s * EOBS * DIN;

        for (int e = 0; e < 2; e++) {
            // t = tanh(h_hi @ Wo1^T + bo1)
            mma_gemm<MODE_TANH, HID, HID><<<gEuler, 256, SMEM_DYN>>>(
                h_hi, Wo1h, nullptr, nullptr,
                bo1, nullptr, nullptr, nullptr, t_hi, nullptr, nullptr, nullptr, nullptr);
            // h = (h_hi+h_lo) + DT*(t @ Wo2^T + bo2)   (state kept hi+lo)
            mma_gemm<MODE_EULER, HID, HID><<<gEuler, 256, SMEM_DYN>>>(
                t_hi, Wo2h, nullptr, nullptr,
                bo2, nullptr, h_hi, h_lo, h_hi, h_lo, nullptr, nullptr, nullptr);
        }
        // p1 = relu(h_hi[idx] @ Wp1^T + bp1)
        mma_gemm<MODE_RELU_G, HID, HID><<<gObs, 256, SMEM_DYN>>>(
            h_hi, Wp1h, nullptr, nullptr,
            bp1, nullptr, nullptr, nullptr, p1_hi, nullptr, is, nullptr, nullptr);
        // loss += sum |X - (p1 @ Wp2^T + bp2)| * M ; totm += sum M
        mma_gemm<MODE_LOSS, HID, DIN><<<gLoss, 256, SMEM_DYN>>>(
            p1_hi, Wp2h, nullptr, nullptr,
            bp2, nullptr, nullptr, nullptr, nullptr, nullptr, nullptr, Xs, Ms);
        // hn = tanh([X | h_hi[idx]] @ [Wih | Whh]^T + b_ih + b_hh)   (K = 640)
        mma_gemm<MODE_RNN, 640, HID><<<gObs, 256, SMEM_DYN>>>(
            Xhs, Wih, h_hi, Whh,
            b_ih, b_hh, nullptr, nullptr, hn_hi, hn_lo, is, nullptr, nullptr);
        // h[idx] = hn  (hi+lo)
        scatter_kernel<<<EOBS, 128>>>(is);
    }
    // prop_to_end Euler steps are output-invariant -> skipped.

    final_kernel<<<1, 1>>>((float*)d_out);
}